// round 5
// baseline (speedup 1.0000x reference)
#include <cuda_runtime.h>

// LocalCosineSimilarity — streaming separable box filter.
// x, y: [8, 3, 1024, 1024] f32.  out: [8, 1024, 1024] f32.
//
// Each CTA: 128-wide strip x 128-row chunk. Rows streamed one at a time:
//   load+channel-reduce -> smem row (double-buffered) -> horizontal 11-tap
//   -> vertical sliding window (smem ring of 11 horizontal sums) -> store.

#define IMG_W  1024
#define IMG_H  1024
#define KW     11
#define HALO   5
#define TW     128               // output strip width
#define RW     138               // input width incl. halo
#define NT     160               // threads (5 warps): 138 load, 128 compute
#define CH     128               // output rows per CTA
#define NROWS  (CH + 2*HALO)     // input rows streamed

__global__ void __launch_bounds__(NT)
lcs_stream_kernel(const float* __restrict__ xg, const float* __restrict__ yg,
                  float* __restrict__ outg)
{
    __shared__ float rbuf[2][3][NT];     // per-row channel-reduced products (dbl-buffered)
    __shared__ float ring[KW][3][TW];    // last 11 horizontal sums per output column

    const int t   = threadIdx.x;
    const int gx0 = blockIdx.x * TW;
    const int gy0 = blockIdx.y * CH;
    const int b   = blockIdx.z;

    const size_t HW = (size_t)IMG_W * IMG_H;
    const float* xb = xg + (size_t)b * 3 * HW;
    const float* yb = yg + (size_t)b * 3 * HW;
    float* outb = outg + (size_t)b * HW;

    // zero the ring
    if (t < TW) {
        #pragma unroll
        for (int s = 0; s < KW; ++s) {
            ring[s][0][t] = 0.f; ring[s][1][t] = 0.f; ring[s][2][t] = 0.f;
        }
    }
    __syncthreads();

    float sxx = 0.f, syy = 0.f, sxy = 0.f;   // vertical running sums (per output col)

    for (int r = 0; r < NROWS; ++r) {
        const int pb = r & 1;
        const int gy = gy0 - HALO + r;

        // ---- load + channel reduce one input row (threads 0..137) ----
        float pxx = 0.f, pyy = 0.f, pxy = 0.f;
        if (t < RW) {
            const int gx = gx0 - HALO + t;
            if ((unsigned)gy < (unsigned)IMG_H && (unsigned)gx < (unsigned)IMG_W) {
                const size_t base = (size_t)gy * IMG_W + gx;
                #pragma unroll
                for (int ch = 0; ch < 3; ++ch) {
                    const float xv = __ldg(xb + (size_t)ch * HW + base);
                    const float yv = __ldg(yb + (size_t)ch * HW + base);
                    pxx = fmaf(xv, xv, pxx);
                    pyy = fmaf(yv, yv, pyy);
                    pxy = fmaf(xv, yv, pxy);
                }
            }
            rbuf[pb][0][t] = pxx;
            rbuf[pb][1][t] = pyy;
            rbuf[pb][2][t] = pxy;
        }
        __syncthreads();

        // ---- horizontal 11-tap + vertical sliding window (threads 0..127) ----
        if (t < TW) {
            float hxx = 0.f, hyy = 0.f, hxy = 0.f;
            #pragma unroll
            for (int k = 0; k < KW; ++k) {
                hxx += rbuf[pb][0][t + k];
                hyy += rbuf[pb][1][t + k];
                hxy += rbuf[pb][2][t + k];
            }
            const int slot = r % KW;
            sxx += hxx - ring[slot][0][t]; ring[slot][0][t] = hxx;
            syy += hyy - ring[slot][1][t]; ring[slot][1][t] = hyy;
            sxy += hxy - ring[slot][2][t]; ring[slot][2][t] = hxy;

            if (r >= 2 * HALO) {
                const int gyo = gy0 + r - 2 * HALO;
                outb[(size_t)gyo * IMG_W + gx0 + t] =
                    sxy / (sqrtf(sxx) * sqrtf(syy) + 1e-6f);
            }
        }
        // no second barrier needed: next iteration writes the other rbuf parity,
        // and this iteration's barrier already orders those writes after the
        // previous iteration's reads of that parity.
    }
}

extern "C" void kernel_launch(void* const* d_in, const int* in_sizes, int n_in,
                              void* d_out, int out_size)
{
    const float* x = (const float*)d_in[0];
    const float* y = (const float*)d_in[1];
    float* out = (float*)d_out;

    dim3 grid(IMG_W / TW,        // 8
              IMG_H / CH,        // 8
              8);                // batch
    lcs_stream_kernel<<<grid, NT>>>(x, y, out);
}

// round 6
// speedup vs baseline: 1.5672x; 1.5672x over previous
#include <cuda_runtime.h>

// LocalCosineSimilarity — warp-autonomous streaming box filter.
// Horizontal 11-tap via warp-shuffle prefix sums (no smem, no barriers).
// Vertical 11-tap via per-lane-owned smem ring + register running sums.
// Next-row values prefetched into registers to overlap LDG latency with
// the shuffle chain.

#define IMG_W  1024
#define IMG_H  1024
#define KW     11
#define HALO   5
#define WCOLS  22                 // output cols per warp (lanes 5..26)
#define NWARP  4
#define NT     (NWARP * 32)       // 128
#define CTAC   (NWARP * WCOLS)    // 88 output cols per CTA
#define CH     64                 // output rows per CTA
#define NR     (CH + 2 * HALO)    // 74 input rows streamed

__global__ void __launch_bounds__(NT, 8)
lcs_warp_kernel(const float* __restrict__ xg, const float* __restrict__ yg,
                float* __restrict__ outg)
{
    __shared__ float ring[KW][3][CTAC];   // 11.6 KB; each lane owns one column

    const int tid  = threadIdx.x;
    const int lane = tid & 31;
    const int w    = tid >> 5;

    const int gy0  = blockIdx.y * CH;
    const int b    = blockIdx.z;
    const int c_in = blockIdx.x * CTAC + w * WCOLS + lane - HALO;  // col this lane loads

    const size_t HW = (size_t)IMG_W * IMG_H;
    const float* xb = xg + (size_t)b * 3 * HW;
    const float* yb = yg + (size_t)b * 3 * HW;
    float* outb = outg + (size_t)b * HW;

    const bool colv   = (unsigned)c_in < (unsigned)IMG_W;
    const bool active = (lane >= HALO) && (lane < HALO + WCOLS) && colv;
    const int  rcol   = w * WCOLS + (lane - HALO);

    // zero the ring (each lane only ever touches its own column afterwards)
    for (int i = tid; i < KW * 3 * CTAC; i += NT)
        ((float*)ring)[i] = 0.f;
    __syncthreads();   // only barrier in the kernel

    const int cc = min(max(c_in, 0), IMG_W - 1);
    const float* xp = xb + cc;
    const float* yp = yb + cc;

    // ---- prefetch row 0 products ----
    float nxx, nyy, nxy;
    {
        const int gy = gy0 - HALO;
        nxx = nyy = nxy = 0.f;
        if (colv && (unsigned)gy < (unsigned)IMG_H) {
            const size_t base = (size_t)gy * IMG_W;
            #pragma unroll
            for (int ch = 0; ch < 3; ++ch) {
                const float xv = __ldg(xp + (size_t)ch * HW + base);
                const float yv = __ldg(yp + (size_t)ch * HW + base);
                nxx = fmaf(xv, xv, nxx);
                nyy = fmaf(yv, yv, nyy);
                nxy = fmaf(xv, yv, nxy);
            }
        }
    }

    float sxx = 0.f, syy = 0.f, sxy = 0.f;
    int slot = 0;

    #pragma unroll 2
    for (int r = 0; r < NR; ++r) {
        // consume prefetched row r
        float Pxx = nxx, Pyy = nyy, Pxy = nxy;

        // ---- prefetch row r+1 (overlaps the shuffle chain below) ----
        nxx = nyy = nxy = 0.f;
        {
            const int gy = gy0 - HALO + r + 1;
            if ((r + 1 < NR) && colv && (unsigned)gy < (unsigned)IMG_H) {
                const size_t base = (size_t)gy * IMG_W;
                #pragma unroll
                for (int ch = 0; ch < 3; ++ch) {
                    const float xv = __ldg(xp + (size_t)ch * HW + base);
                    const float yv = __ldg(yp + (size_t)ch * HW + base);
                    nxx = fmaf(xv, xv, nxx);
                    nyy = fmaf(yv, yv, nyy);
                    nxy = fmaf(xv, yv, nxy);
                }
            }
        }

        // ---- inclusive prefix sum over lanes (3 independent chains) ----
        #pragma unroll
        for (int o = 1; o < 32; o <<= 1) {
            const float a0 = __shfl_up_sync(0xffffffffu, Pxx, o);
            const float a1 = __shfl_up_sync(0xffffffffu, Pyy, o);
            const float a2 = __shfl_up_sync(0xffffffffu, Pxy, o);
            if (lane >= o) { Pxx += a0; Pyy += a1; Pxy += a2; }
        }

        // ---- 11-wide window sum: h[l] = P[l+5] - P[l-6] ----
        float hxx = __shfl_down_sync(0xffffffffu, Pxx, HALO);
        float hyy = __shfl_down_sync(0xffffffffu, Pyy, HALO);
        float hxy = __shfl_down_sync(0xffffffffu, Pxy, HALO);
        const float lxx = __shfl_up_sync(0xffffffffu, Pxx, HALO + 1);
        const float lyy = __shfl_up_sync(0xffffffffu, Pyy, HALO + 1);
        const float lxy = __shfl_up_sync(0xffffffffu, Pxy, HALO + 1);
        if (lane >= HALO + 1) { hxx -= lxx; hyy -= lyy; hxy -= lxy; }

        // ---- vertical sliding window + finalize ----
        if (active) {
            sxx += hxx - ring[slot][0][rcol];  ring[slot][0][rcol] = hxx;
            syy += hyy - ring[slot][1][rcol];  ring[slot][1][rcol] = hyy;
            sxy += hxy - ring[slot][2][rcol];  ring[slot][2][rcol] = hxy;

            if (r >= 2 * HALO) {
                const int ro = gy0 + r - 2 * HALO;
                outb[(size_t)ro * IMG_W + c_in] =
                    sxy / (sqrtf(sxx) * sqrtf(syy) + 1e-6f);
            }
        }
        if (++slot == KW) slot = 0;
    }
}

extern "C" void kernel_launch(void* const* d_in, const int* in_sizes, int n_in,
                              void* d_out, int out_size)
{
    const float* x = (const float*)d_in[0];
    const float* y = (const float*)d_in[1];
    float* out = (float*)d_out;

    dim3 grid((IMG_W + CTAC - 1) / CTAC,   // 12
              IMG_H / CH,                  // 16
              8);                          // batch
    lcs_warp_kernel<<<grid, NT>>>(x, y, out);
}